// round 11
// baseline (speedup 1.0000x reference)
#include <cuda_runtime.h>
#include <cuda_fp16.h>
#include <cstdint>
#include <cstddef>

#define NTOK 8192
#define DIN  4096
#define DOUT 4096

// -------- device scratch --------
__device__ __half g_xh[(size_t)NTOK * DIN];    // fp16(x)
__device__ __half g_Wv2[(size_t)512 * DIN];    // [s 512][k 4096]  fp16(sign(V_b)*v2_b[k])
__device__ __half g_Wu2[(size_t)DOUT * 512];   // [n 4096][k 512]  fp16(sign(U_b)*u1_b[n])
__device__ __half g_h[(size_t)NTOK * 512];     // fp16 intermediate (v1*u2 applied)

// -------- helpers --------
__device__ __forceinline__ uint32_t smem_u32(const void* p) {
    uint32_t a;
    asm("{ .reg .u64 t; cvta.to.shared.u64 t, %1; cvt.u32.u64 %0, t; }" : "=r"(a) : "l"(p));
    return a;
}
__device__ __forceinline__ void cpa16(uint32_t dst, const void* src) {
    asm volatile("cp.async.cg.shared.global [%0], [%1], 16;" :: "r"(dst), "l"(src) : "memory");
}
#define CP_COMMIT() asm volatile("cp.async.commit_group;" ::: "memory")
#define CP_WAIT1()  asm volatile("cp.async.wait_group 1;" ::: "memory")

__device__ __forceinline__ void mma_fp16(float* c, const uint32_t* a, uint32_t b0, uint32_t b1) {
    asm volatile(
        "mma.sync.aligned.m16n8k16.row.col.f32.f16.f16.f32 "
        "{%0,%1,%2,%3}, {%4,%5,%6,%7}, {%8,%9}, {%0,%1,%2,%3};"
        : "+f"(c[0]), "+f"(c[1]), "+f"(c[2]), "+f"(c[3])
        : "r"(a[0]), "r"(a[1]), "r"(a[2]), "r"(a[3]), "r"(b0), "r"(b1));
}
#define LDSM_X4(r0, r1, r2, r3, addr) \
    asm volatile("ldmatrix.sync.aligned.m8n8.x4.shared.b16 {%0,%1,%2,%3}, [%4];" \
                 : "=r"(r0), "=r"(r1), "=r"(r2), "=r"(r3) : "r"(addr))

// -------- smem geometry --------
// ktile = 64 halves (128B data), row stride 144B (conflict-free for ldmatrix).
// A tile: 128 rows x 144B -> 18432B; B tile: 128 rows x 144B -> 18432B
// stage = 36864B, 3 stages = 110592B -> 2 CTAs/SM
#define BOFF 18432
#define STG  36864
#define GSMEM (3 * STG + 512)

// -------- kc: x -> fp16 --------
__global__ void kc_kernel(const float* __restrict__ x) {
    size_t i = ((size_t)blockIdx.x * blockDim.x + threadIdx.x) * 8;
    if (i >= (size_t)NTOK * DIN) return;
    float4 a = *reinterpret_cast<const float4*>(x + i);
    float4 b = *reinterpret_cast<const float4*>(x + i + 4);
    __half2 h0 = __floats2half2_rn(a.x, a.y);
    __half2 h1 = __floats2half2_rn(a.z, a.w);
    __half2 h2 = __floats2half2_rn(b.x, b.y);
    __half2 h3 = __floats2half2_rn(b.z, b.w);
    uint2 o, o2;
    o.x  = *reinterpret_cast<uint32_t*>(&h0);
    o.y  = *reinterpret_cast<uint32_t*>(&h1);
    o2.x = *reinterpret_cast<uint32_t*>(&h2);
    o2.y = *reinterpret_cast<uint32_t*>(&h3);
    *reinterpret_cast<uint2*>(g_xh + i) = o;
    *reinterpret_cast<uint2*>(g_xh + i + 4) = o2;
}

// -------- kw: fold scales into sign weights (fp16) --------
__global__ void kw_kernel(const float* __restrict__ V,  const float* __restrict__ VR,
                          const float* __restrict__ U,  const float* __restrict__ UR,
                          const float* __restrict__ v2, const float* __restrict__ v2R,
                          const float* __restrict__ u1, const float* __restrict__ u1R) {
    int i = blockIdx.x * blockDim.x + threadIdx.x;
    if (i >= 512 * DIN) return;
    {
        int s = i >> 12, k = i & (DIN - 1);
        float w  = (s < 256) ? V[(size_t)s * DIN + k] : VR[(size_t)(s - 256) * DIN + k];
        float sv = (s < 256) ? v2[k] : v2R[k];
        float sg = (w > 0.f) ? 1.f : ((w < 0.f) ? -1.f : 0.f);
        g_Wv2[i] = __float2half(sg * sv);
    }
    {
        int n = i >> 9, kk = i & 511;
        float w  = (kk < 256) ? U[(size_t)n * 256 + kk] : UR[(size_t)n * 256 + (kk - 256)];
        float su = (kk < 256) ? u1[n] : u1R[n];
        float sg = (w > 0.f) ? 1.f : ((w < 0.f) ? -1.f : 0.f);
        g_Wu2[i] = __float2half(sg * su);
    }
}

// ldmatrix lane-address helpers (144B row stride, conflict-free)
__device__ __forceinline__ uint32_t a_lane_off(int wm, int lane) {
    return (uint32_t)((wm * 32 + (lane & 15)) * 144 + (lane >> 4) * 16);
}
__device__ __forceinline__ uint32_t b_lane_off(int wn, int lane) {
    return (uint32_t)((wn * 64 + ((lane >> 4) << 3) + (lane & 7)) * 144 + (((lane >> 3) & 1) << 4));
}

// -------- k1: h[m, 512] = fp16( (x @ Wv2^T) * (v1*u2) ) --------
// grid (64, 4): br = by>>1, nb = (by&1)*128. CTA tile 128x128, ktile 64, 64 iters.
__global__ void __launch_bounds__(256, 2) k1_kernel(
    const float* __restrict__ v1a, const float* __restrict__ u2a,
    const float* __restrict__ v1b, const float* __restrict__ u2b)
{
    extern __shared__ char sm[];
    const uint32_t smb = smem_u32(sm);
    const int tid = threadIdx.x, warp = tid >> 5, lane = tid & 31;
    const int r = lane >> 2, q = lane & 3;
    const int wm = warp >> 1, wn = warp & 1;
    const int m0 = blockIdx.x * 128;
    const int by = blockIdx.y;
    const int br = by >> 1, nb = (by & 1) * 128;

    float* sc = reinterpret_cast<float*>(sm + 3 * STG);
    if (tid < 128) {
        const float* v1 = br ? v1b : v1a;
        const float* u2 = br ? u2b : u2a;
        sc[tid] = v1[nb + tid] * u2[nb + tid];
    }
    const int row = tid >> 1, half = tid & 1;
    const uint32_t aoff = a_lane_off(wm, lane);
    const uint32_t boff = b_lane_off(wn, lane) + BOFF;

    auto issue = [&](int j) {
        if (j < 64) {
            const int s3 = j % 3, k0 = j * 64;
            uint32_t xd = smb + s3 * STG + row * 144 + half * 64;
            const __half* xs = g_xh + (size_t)(m0 + row) * DIN + k0 + half * 32;
            cpa16(xd, xs);       cpa16(xd + 16, xs + 8);
            cpa16(xd + 32, xs + 16); cpa16(xd + 48, xs + 24);
            uint32_t bd = smb + s3 * STG + BOFF + row * 144 + half * 64;
            const __half* bsrc = g_Wv2 + (size_t)(br * 256 + nb + row) * DIN + k0 + half * 32;
            cpa16(bd, bsrc);       cpa16(bd + 16, bsrc + 8);
            cpa16(bd + 32, bsrc + 16); cpa16(bd + 48, bsrc + 24);
        }
        CP_COMMIT();
    };
    issue(0); issue(1);

    float acc[2][8][4];
#pragma unroll
    for (int a = 0; a < 2; a++)
#pragma unroll
        for (int b = 0; b < 8; b++)
#pragma unroll
            for (int c = 0; c < 4; c++) acc[a][b][c] = 0.f;

    for (int it = 0; it < 64; ++it) {
        CP_WAIT1();
        __syncthreads();
        issue(it + 2);
        const uint32_t stg = smb + (it % 3) * STG;
#pragma unroll
        for (int s16 = 0; s16 < 4; s16++) {
            uint32_t a[2][4];
            LDSM_X4(a[0][0], a[0][1], a[0][2], a[0][3], stg + aoff + s16 * 32);
            LDSM_X4(a[1][0], a[1][1], a[1][2], a[1][3], stg + aoff + 16 * 144 + s16 * 32);
#pragma unroll
            for (int ntp = 0; ntp < 4; ntp++) {
                uint32_t b[4];
                LDSM_X4(b[0], b[1], b[2], b[3], stg + boff + ntp * (16 * 144) + s16 * 32);
                mma_fp16(acc[0][2 * ntp],     a[0], b[0], b[1]);
                mma_fp16(acc[1][2 * ntp],     a[1], b[0], b[1]);
                mma_fp16(acc[0][2 * ntp + 1], a[0], b[2], b[3]);
                mma_fp16(acc[1][2 * ntp + 1], a[1], b[2], b[3]);
            }
        }
    }

    // epilogue: scale by (v1*u2), convert fp16, store h
#pragma unroll
    for (int mt = 0; mt < 2; mt++) {
#pragma unroll
        for (int nt = 0; nt < 8; nt++) {
            const int rw = m0 + wm * 32 + mt * 16 + r;
            const int cl = wn * 64 + nt * 8 + 2 * q;
            const int col = br * 256 + nb + cl;
            const float s0 = sc[cl], s1 = sc[cl + 1];
            __half2 p0 = __floats2half2_rn(acc[mt][nt][0] * s0, acc[mt][nt][1] * s1);
            __half2 p1 = __floats2half2_rn(acc[mt][nt][2] * s0, acc[mt][nt][3] * s1);
            *reinterpret_cast<uint32_t*>(g_h + (size_t)rw * 512 + col) =
                *reinterpret_cast<uint32_t*>(&p0);
            *reinterpret_cast<uint32_t*>(g_h + (size_t)(rw + 8) * 512 + col) =
                *reinterpret_cast<uint32_t*>(&p1);
        }
    }
}

// -------- k2: y[m, n] = h @ Wu2^T + bias --------
// grid (64, 32). CTA tile 128x128, K=512, ktile 64, 8 iters.
__global__ void __launch_bounds__(256, 2) k2_kernel(
    const float* __restrict__ bias, float* __restrict__ out)
{
    extern __shared__ char sm[];
    const uint32_t smb = smem_u32(sm);
    const int tid = threadIdx.x, warp = tid >> 5, lane = tid & 31;
    const int r = lane >> 2, q = lane & 3;
    const int wm = warp >> 1, wn = warp & 1;
    const int m0 = blockIdx.x * 128;
    const int n0 = blockIdx.y * 128;

    float* bs = reinterpret_cast<float*>(sm + 3 * STG);
    if (tid < 128) bs[tid] = bias[n0 + tid];
    const int row = tid >> 1, half = tid & 1;
    const uint32_t aoff = a_lane_off(wm, lane);
    const uint32_t boff = b_lane_off(wn, lane) + BOFF;

    auto issue = [&](int j) {
        if (j < 8) {
            const int s3 = j % 3, k0 = j * 64;
            uint32_t xd = smb + s3 * STG + row * 144 + half * 64;
            const __half* xs = g_h + (size_t)(m0 + row) * 512 + k0 + half * 32;
            cpa16(xd, xs);       cpa16(xd + 16, xs + 8);
            cpa16(xd + 32, xs + 16); cpa16(xd + 48, xs + 24);
            uint32_t bd = smb + s3 * STG + BOFF + row * 144 + half * 64;
            const __half* bsrc = g_Wu2 + (size_t)(n0 + row) * 512 + k0 + half * 32;
            cpa16(bd, bsrc);       cpa16(bd + 16, bsrc + 8);
            cpa16(bd + 32, bsrc + 16); cpa16(bd + 48, bsrc + 24);
        }
        CP_COMMIT();
    };
    issue(0); issue(1);

    float acc[2][8][4];
#pragma unroll
    for (int a = 0; a < 2; a++)
#pragma unroll
        for (int b = 0; b < 8; b++)
#pragma unroll
            for (int c = 0; c < 4; c++) acc[a][b][c] = 0.f;

    for (int it = 0; it < 8; ++it) {
        CP_WAIT1();
        __syncthreads();
        issue(it + 2);
        const uint32_t stg = smb + (it % 3) * STG;
#pragma unroll
        for (int s16 = 0; s16 < 4; s16++) {
            uint32_t a[2][4];
            LDSM_X4(a[0][0], a[0][1], a[0][2], a[0][3], stg + aoff + s16 * 32);
            LDSM_X4(a[1][0], a[1][1], a[1][2], a[1][3], stg + aoff + 16 * 144 + s16 * 32);
#pragma unroll
            for (int ntp = 0; ntp < 4; ntp++) {
                uint32_t b[4];
                LDSM_X4(b[0], b[1], b[2], b[3], stg + boff + ntp * (16 * 144) + s16 * 32);
                mma_fp16(acc[0][2 * ntp],     a[0], b[0], b[1]);
                mma_fp16(acc[1][2 * ntp],     a[1], b[0], b[1]);
                mma_fp16(acc[0][2 * ntp + 1], a[0], b[2], b[3]);
                mma_fp16(acc[1][2 * ntp + 1], a[1], b[2], b[3]);
            }
        }
    }

    // epilogue: + bias (u1 folded into Wu2)
#pragma unroll
    for (int mt = 0; mt < 2; mt++) {
#pragma unroll
        for (int nt = 0; nt < 8; nt++) {
            const int rw = m0 + wm * 32 + mt * 16 + r;
            const int cl = wn * 64 + nt * 8 + 2 * q;
            const int col = n0 + cl;
            float2 p0, p1;
            p0.x = acc[mt][nt][0] + bs[cl];
            p0.y = acc[mt][nt][1] + bs[cl + 1];
            p1.x = acc[mt][nt][2] + bs[cl];
            p1.y = acc[mt][nt][3] + bs[cl + 1];
            *reinterpret_cast<float2*>(out + (size_t)rw * DOUT + col) = p0;
            *reinterpret_cast<float2*>(out + (size_t)(rw + 8) * DOUT + col) = p1;
        }
    }
}

extern "C" void kernel_launch(void* const* d_in, const int* in_sizes, int n_in,
                              void* d_out, int out_size) {
    const float* x    = (const float*)d_in[0];
    const float* V    = (const float*)d_in[1];
    const float* U    = (const float*)d_in[2];
    const float* v1   = (const float*)d_in[3];
    const float* v2   = (const float*)d_in[4];
    const float* u1   = (const float*)d_in[5];
    const float* u2   = (const float*)d_in[6];
    const float* VR   = (const float*)d_in[7];
    const float* UR   = (const float*)d_in[8];
    const float* v1R  = (const float*)d_in[9];
    const float* v2R  = (const float*)d_in[10];
    const float* u1R  = (const float*)d_in[11];
    const float* u2R  = (const float*)d_in[12];
    const float* bias = (const float*)d_in[13];
    float* out = (float*)d_out;

    static bool attr_set = false;
    if (!attr_set) {
        cudaFuncSetAttribute(k1_kernel, cudaFuncAttributeMaxDynamicSharedMemorySize, GSMEM);
        cudaFuncSetAttribute(k2_kernel, cudaFuncAttributeMaxDynamicSharedMemorySize, GSMEM);
        attr_set = true;
    }

    kc_kernel<<<(NTOK * (size_t)DIN) / (256 * 8), 256>>>(x);
    kw_kernel<<<8192, 256>>>(V, VR, U, UR, v2, v2R, u1, u1R);
    k1_kernel<<<dim3(NTOK / 128, 4), 256, GSMEM>>>(v1, u2, v1R, u2R);
    k2_kernel<<<dim3(NTOK / 128, DOUT / 128), 256, GSMEM>>>(bias, out);
}

// round 14
// speedup vs baseline: 1.3236x; 1.3236x over previous
#include <cuda_runtime.h>
#include <cuda_fp16.h>
#include <cstdint>
#include <cstddef>

#define NTOK 8192
#define DIN  4096
#define DOUT 4096

// -------- device scratch --------
__device__ __half g_xh[(size_t)NTOK * DIN];    // fp16(x)
__device__ __half g_Wv2[(size_t)512 * DIN];    // [s 512][k 4096]  fp16(sign(V_b)*v2_b[k])
__device__ __half g_Wu2[(size_t)DOUT * 512];   // [n 4096][k 512]  fp16(sign(U_b)*u1_b[n])
__device__ __half g_h[(size_t)NTOK * 512];     // fp16 intermediate (v1*u2 applied)

// -------- helpers --------
__device__ __forceinline__ uint32_t smem_u32(const void* p) {
    uint32_t a;
    asm("{ .reg .u64 t; cvta.to.shared.u64 t, %1; cvt.u32.u64 %0, t; }" : "=r"(a) : "l"(p));
    return a;
}
__device__ __forceinline__ void cpa16(uint32_t dst, const void* src) {
    asm volatile("cp.async.cg.shared.global [%0], [%1], 16;" :: "r"(dst), "l"(src) : "memory");
}
#define CP_COMMIT() asm volatile("cp.async.commit_group;" ::: "memory")
#define CP_WAIT2()  asm volatile("cp.async.wait_group 2;" ::: "memory")

__device__ __forceinline__ void mma_fp16(float* c, const uint32_t* a, uint32_t b0, uint32_t b1) {
    asm volatile(
        "mma.sync.aligned.m16n8k16.row.col.f32.f16.f16.f32 "
        "{%0,%1,%2,%3}, {%4,%5,%6,%7}, {%8,%9}, {%0,%1,%2,%3};"
        : "+f"(c[0]), "+f"(c[1]), "+f"(c[2]), "+f"(c[3])
        : "r"(a[0]), "r"(a[1]), "r"(a[2]), "r"(a[3]), "r"(b0), "r"(b1));
}
#define LDSM_X4(r0, r1, r2, r3, addr) \
    asm volatile("ldmatrix.sync.aligned.m8n8.x4.shared.b16 {%0,%1,%2,%3}, [%4];" \
                 : "=r"(r0), "=r"(r1), "=r"(r2), "=r"(r3) : "r"(addr))

// -------- smem geometry --------
// ktile = 32 halves (64B data), row stride 80B (conflict-free).
// A tile: 128 rows x 80B -> 10240B; B tile: 128 rows x 80B -> 10240B
// stage = 20480B, 4 stages = 81920B -> 2 CTAs/SM (128 threads each)
#define BOFF 10240
#define STG  20480
#define GSMEM (4 * STG + 512)

// -------- kc: x -> fp16 --------
__global__ void kc_kernel(const float* __restrict__ x) {
    size_t i = ((size_t)blockIdx.x * blockDim.x + threadIdx.x) * 8;
    if (i >= (size_t)NTOK * DIN) return;
    float4 a = *reinterpret_cast<const float4*>(x + i);
    float4 b = *reinterpret_cast<const float4*>(x + i + 4);
    __half2 h0 = __floats2half2_rn(a.x, a.y);
    __half2 h1 = __floats2half2_rn(a.z, a.w);
    __half2 h2 = __floats2half2_rn(b.x, b.y);
    __half2 h3 = __floats2half2_rn(b.z, b.w);
    uint2 o, o2;
    o.x  = *reinterpret_cast<uint32_t*>(&h0);
    o.y  = *reinterpret_cast<uint32_t*>(&h1);
    o2.x = *reinterpret_cast<uint32_t*>(&h2);
    o2.y = *reinterpret_cast<uint32_t*>(&h3);
    *reinterpret_cast<uint2*>(g_xh + i) = o;
    *reinterpret_cast<uint2*>(g_xh + i + 4) = o2;
}

// -------- kw: fold scales into sign weights (fp16) --------
__global__ void kw_kernel(const float* __restrict__ V,  const float* __restrict__ VR,
                          const float* __restrict__ U,  const float* __restrict__ UR,
                          const float* __restrict__ v2, const float* __restrict__ v2R,
                          const float* __restrict__ u1, const float* __restrict__ u1R) {
    int i = blockIdx.x * blockDim.x + threadIdx.x;
    if (i >= 512 * DIN) return;
    {
        int s = i >> 12, k = i & (DIN - 1);
        float w  = (s < 256) ? V[(size_t)s * DIN + k] : VR[(size_t)(s - 256) * DIN + k];
        float sv = (s < 256) ? v2[k] : v2R[k];
        float sg = (w > 0.f) ? 1.f : ((w < 0.f) ? -1.f : 0.f);
        g_Wv2[i] = __float2half(sg * sv);
    }
    {
        int n = i >> 9, kk = i & 511;
        float w  = (kk < 256) ? U[(size_t)n * 256 + kk] : UR[(size_t)n * 256 + (kk - 256)];
        float su = (kk < 256) ? u1[n] : u1R[n];
        float sg = (w > 0.f) ? 1.f : ((w < 0.f) ? -1.f : 0.f);
        g_Wu2[i] = __float2half(sg * su);
    }
}

// ldmatrix lane-address helpers (80B row stride, conflict-free in 8-lane phases)
__device__ __forceinline__ uint32_t a_lane_off(int wm, int lane) {
    return (uint32_t)((wm * 64 + (lane & 15)) * 80 + (lane >> 4) * 16);
}
__device__ __forceinline__ uint32_t b_lane_off(int wn, int lane) {
    return (uint32_t)((wn * 64 + ((lane >> 4) << 3) + (lane & 7)) * 80 + (((lane >> 3) & 1) << 4));
}

// -------- k1: h[m, 512] = fp16( (x @ Wv2^T) * (v1*u2) ) --------
// grid (64, 4): br = by>>1, nb = (by&1)*128. CTA 128x128, 4 warps of 64x64, ktile 32.
__global__ void __launch_bounds__(128, 2) k1_kernel(
    const float* __restrict__ v1a, const float* __restrict__ u2a,
    const float* __restrict__ v1b, const float* __restrict__ u2b)
{
    extern __shared__ char sm[];
    const uint32_t smb = smem_u32(sm);
    const int tid = threadIdx.x, warp = tid >> 5, lane = tid & 31;
    const int r = lane >> 2, q = lane & 3;
    const int wm = warp >> 1, wn = warp & 1;
    const int m0 = blockIdx.x * 128;
    const int by = blockIdx.y;
    const int br = by >> 1, nb = (by & 1) * 128;

    float* sc = reinterpret_cast<float*>(sm + 4 * STG);
    {
        const float* v1 = br ? v1b : v1a;
        const float* u2 = br ? u2b : u2a;
        sc[tid] = v1[nb + tid] * u2[nb + tid];
    }
    const uint32_t aoff = a_lane_off(wm, lane);
    const uint32_t boff = b_lane_off(wn, lane) + BOFF;

    auto issue = [&](int j) {
        if (j < 128) {
            const int s4 = j & 3, k0 = j * 32;
            uint32_t xd = smb + s4 * STG + tid * 80;
            const __half* xs = g_xh + (size_t)(m0 + tid) * DIN + k0;
            cpa16(xd, xs);       cpa16(xd + 16, xs + 8);
            cpa16(xd + 32, xs + 16); cpa16(xd + 48, xs + 24);
            uint32_t bd = smb + s4 * STG + BOFF + tid * 80;
            const __half* bsrc = g_Wv2 + (size_t)(br * 256 + nb + tid) * DIN + k0;
            cpa16(bd, bsrc);       cpa16(bd + 16, bsrc + 8);
            cpa16(bd + 32, bsrc + 16); cpa16(bd + 48, bsrc + 24);
        }
        CP_COMMIT();
    };
    issue(0); issue(1); issue(2);

    float acc[4][8][4];
#pragma unroll
    for (int a = 0; a < 4; a++)
#pragma unroll
        for (int b = 0; b < 8; b++)
#pragma unroll
            for (int c = 0; c < 4; c++) acc[a][b][c] = 0.f;

    for (int it = 0; it < 128; ++it) {
        CP_WAIT2();
        __syncthreads();
        issue(it + 3);
        const uint32_t stg = smb + (it & 3) * STG;
#pragma unroll
        for (int s16 = 0; s16 < 2; s16++) {
            uint32_t a[4][4];
#pragma unroll
            for (int mt = 0; mt < 4; mt++)
                LDSM_X4(a[mt][0], a[mt][1], a[mt][2], a[mt][3],
                        stg + aoff + mt * (16 * 80) + s16 * 32);
#pragma unroll
            for (int ntp = 0; ntp < 4; ntp++) {
                uint32_t b[4];
                LDSM_X4(b[0], b[1], b[2], b[3], stg + boff + ntp * (16 * 80) + s16 * 32);
#pragma unroll
                for (int mt = 0; mt < 4; mt++) {
                    mma_fp16(acc[mt][2 * ntp],     a[mt], b[0], b[1]);
                    mma_fp16(acc[mt][2 * ntp + 1], a[mt], b[2], b[3]);
                }
            }
        }
    }

    // epilogue: scale by (v1*u2), convert fp16, store h
#pragma unroll
    for (int mt = 0; mt < 4; mt++) {
#pragma unroll
        for (int nt = 0; nt < 8; nt++) {
            const int rw = m0 + wm * 64 + mt * 16 + r;
            const int cl = wn * 64 + nt * 8 + 2 * q;
            const int col = br * 256 + nb + cl;
            const float s0 = sc[cl], s1 = sc[cl + 1];
            __half2 p0 = __floats2half2_rn(acc[mt][nt][0] * s0, acc[mt][nt][1] * s1);
            __half2 p1 = __floats2half2_rn(acc[mt][nt][2] * s0, acc[mt][nt][3] * s1);
            *reinterpret_cast<uint32_t*>(g_h + (size_t)rw * 512 + col) =
                *reinterpret_cast<uint32_t*>(&p0);
            *reinterpret_cast<uint32_t*>(g_h + (size_t)(rw + 8) * 512 + col) =
                *reinterpret_cast<uint32_t*>(&p1);
        }
    }
}

// -------- k2: y[m, n] = h @ Wu2^T + bias --------
// grid (64, 32). CTA 128x128, 4 warps of 64x64, K=512, ktile 32, 16 iters.
__global__ void __launch_bounds__(128, 2) k2_kernel(
    const float* __restrict__ bias, float* __restrict__ out)
{
    extern __shared__ char sm[];
    const uint32_t smb = smem_u32(sm);
    const int tid = threadIdx.x, warp = tid >> 5, lane = tid & 31;
    const int r = lane >> 2, q = lane & 3;
    const int wm = warp >> 1, wn = warp & 1;
    const int m0 = blockIdx.x * 128;
    const int n0 = blockIdx.y * 128;

    float* bs = reinterpret_cast<float*>(sm + 4 * STG);
    bs[tid] = bias[n0 + tid];
    const uint32_t aoff = a_lane_off(wm, lane);
    const uint32_t boff = b_lane_off(wn, lane) + BOFF;

    auto issue = [&](int j) {
        if (j < 16) {
            const int s4 = j & 3, k0 = j * 32;
            uint32_t xd = smb + s4 * STG + tid * 80;
            const __half* xs = g_h + (size_t)(m0 + tid) * 512 + k0;
            cpa16(xd, xs);       cpa16(xd + 16, xs + 8);
            cpa16(xd + 32, xs + 16); cpa16(xd + 48, xs + 24);
            uint32_t bd = smb + s4 * STG + BOFF + tid * 80;
            const __half* bsrc = g_Wu2 + (size_t)(n0 + tid) * 512 + k0;
            cpa16(bd, bsrc);       cpa16(bd + 16, bsrc + 8);
            cpa16(bd + 32, bsrc + 16); cpa16(bd + 48, bsrc + 24);
        }
        CP_COMMIT();
    };
    issue(0); issue(1); issue(2);

    float acc[4][8][4];
#pragma unroll
    for (int a = 0; a < 4; a++)
#pragma unroll
        for (int b = 0; b < 8; b++)
#pragma unroll
            for (int c = 0; c < 4; c++) acc[a][b][c] = 0.f;

    for (int it = 0; it < 16; ++it) {
        CP_WAIT2();
        __syncthreads();
        issue(it + 3);
        const uint32_t stg = smb + (it & 3) * STG;
#pragma unroll
        for (int s16 = 0; s16 < 2; s16++) {
            uint32_t a[4][4];
#pragma unroll
            for (int mt = 0; mt < 4; mt++)
                LDSM_X4(a[mt][0], a[mt][1], a[mt][2], a[mt][3],
                        stg + aoff + mt * (16 * 80) + s16 * 32);
#pragma unroll
            for (int ntp = 0; ntp < 4; ntp++) {
                uint32_t b[4];
                LDSM_X4(b[0], b[1], b[2], b[3], stg + boff + ntp * (16 * 80) + s16 * 32);
#pragma unroll
                for (int mt = 0; mt < 4; mt++) {
                    mma_fp16(acc[mt][2 * ntp],     a[mt], b[0], b[1]);
                    mma_fp16(acc[mt][2 * ntp + 1], a[mt], b[2], b[3]);
                }
            }
        }
    }

    // epilogue: + bias (u1 folded into Wu2)
#pragma unroll
    for (int mt = 0; mt < 4; mt++) {
#pragma unroll
        for (int nt = 0; nt < 8; nt++) {
            const int rw = m0 + wm * 64 + mt * 16 + r;
            const int cl = wn * 64 + nt * 8 + 2 * q;
            const int col = n0 + cl;
            float2 p0, p1;
            p0.x = acc[mt][nt][0] + bs[cl];
            p0.y = acc[mt][nt][1] + bs[cl + 1];
            p1.x = acc[mt][nt][2] + bs[cl];
            p1.y = acc[mt][nt][3] + bs[cl + 1];
            *reinterpret_cast<float2*>(out + (size_t)rw * DOUT + col) = p0;
            *reinterpret_cast<float2*>(out + (size_t)(rw + 8) * DOUT + col) = p1;
        }
    }
}

extern "C" void kernel_launch(void* const* d_in, const int* in_sizes, int n_in,
                              void* d_out, int out_size) {
    const float* x    = (const float*)d_in[0];
    const float* V    = (const float*)d_in[1];
    const float* U    = (const float*)d_in[2];
    const float* v1   = (const float*)d_in[3];
    const float* v2   = (const float*)d_in[4];
    const float* u1   = (const float*)d_in[5];
    const float* u2   = (const float*)d_in[6];
    const float* VR   = (const float*)d_in[7];
    const float* UR   = (const float*)d_in[8];
    const float* v1R  = (const float*)d_in[9];
    const float* v2R  = (const float*)d_in[10];
    const float* u1R  = (const float*)d_in[11];
    const float* u2R  = (const float*)d_in[12];
    const float* bias = (const float*)d_in[13];
    float* out = (float*)d_out;

    static bool attr_set = false;
    if (!attr_set) {
        cudaFuncSetAttribute(k1_kernel, cudaFuncAttributeMaxDynamicSharedMemorySize, GSMEM);
        cudaFuncSetAttribute(k2_kernel, cudaFuncAttributeMaxDynamicSharedMemorySize, GSMEM);
        attr_set = true;
    }

    kc_kernel<<<(NTOK * (size_t)DIN) / (256 * 8), 256>>>(x);
    kw_kernel<<<8192, 256>>>(V, VR, U, UR, v2, v2R, u1, u1R);
    k1_kernel<<<dim3(NTOK / 128, 4), 128, GSMEM>>>(v1, u2, v1R, u2R);
    k2_kernel<<<dim3(NTOK / 128, DOUT / 128), 128, GSMEM>>>(bias, out);
}

// round 15
// speedup vs baseline: 1.7031x; 1.2867x over previous
#include <cuda_runtime.h>
#include <cuda_fp16.h>
#include <cstdint>
#include <cstddef>

#define NTOK 8192
#define DIN  4096
#define DOUT 4096

// -------- device scratch --------
__device__ __half g_xh[(size_t)NTOK * DIN];    // fp16(x)
__device__ __half g_Wv2[(size_t)512 * DIN];    // [s 512][k 4096]  fp16(sign(V_b)*v2_b[k])
__device__ __half g_Wu2[(size_t)DOUT * 512];   // [n 4096][k 512]  fp16(sign(U_b)*u1_b[n])
__device__ __half g_h[(size_t)NTOK * 512];     // fp16 intermediate (v1*u2 applied)

// -------- helpers --------
__device__ __forceinline__ uint32_t smem_u32(const void* p) {
    uint32_t a;
    asm("{ .reg .u64 t; cvta.to.shared.u64 t, %1; cvt.u32.u64 %0, t; }" : "=r"(a) : "l"(p));
    return a;
}
__device__ __forceinline__ void cpa16(uint32_t dst, const void* src) {
    asm volatile("cp.async.cg.shared.global [%0], [%1], 16;" :: "r"(dst), "l"(src) : "memory");
}
#define CP_COMMIT() asm volatile("cp.async.commit_group;" ::: "memory")
#define CP_WAIT3()  asm volatile("cp.async.wait_group 3;" ::: "memory")

__device__ __forceinline__ void mma_fp16(float* c, const uint32_t* a, uint32_t b0, uint32_t b1) {
    asm volatile(
        "mma.sync.aligned.m16n8k16.row.col.f32.f16.f16.f32 "
        "{%0,%1,%2,%3}, {%4,%5,%6,%7}, {%8,%9}, {%0,%1,%2,%3};"
        : "+f"(c[0]), "+f"(c[1]), "+f"(c[2]), "+f"(c[3])
        : "r"(a[0]), "r"(a[1]), "r"(a[2]), "r"(a[3]), "r"(b0), "r"(b1));
}
#define LDSM_X4(r0, r1, r2, r3, addr) \
    asm volatile("ldmatrix.sync.aligned.m8n8.x4.shared.b16 {%0,%1,%2,%3}, [%4];" \
                 : "=r"(r0), "=r"(r1), "=r"(r2), "=r"(r3) : "r"(addr))

// -------- smem geometry --------
// ktile = 32 halves (64B data), row stride 80B (conflict-free).
// A tile: 128 rows x 80B -> 10240B; B tile: 128 rows x 80B -> 10240B
// stage = 20480B, 5 stages = 102400B -> 2 CTAs/SM
#define BOFF 10240
#define STG  20480
#define GSMEM (5 * STG + 512)

// -------- kc: x -> fp16 --------
__global__ void kc_kernel(const float* __restrict__ x) {
    size_t i = ((size_t)blockIdx.x * blockDim.x + threadIdx.x) * 8;
    if (i >= (size_t)NTOK * DIN) return;
    float4 a = *reinterpret_cast<const float4*>(x + i);
    float4 b = *reinterpret_cast<const float4*>(x + i + 4);
    __half2 h0 = __floats2half2_rn(a.x, a.y);
    __half2 h1 = __floats2half2_rn(a.z, a.w);
    __half2 h2 = __floats2half2_rn(b.x, b.y);
    __half2 h3 = __floats2half2_rn(b.z, b.w);
    uint2 o, o2;
    o.x  = *reinterpret_cast<uint32_t*>(&h0);
    o.y  = *reinterpret_cast<uint32_t*>(&h1);
    o2.x = *reinterpret_cast<uint32_t*>(&h2);
    o2.y = *reinterpret_cast<uint32_t*>(&h3);
    *reinterpret_cast<uint2*>(g_xh + i) = o;
    *reinterpret_cast<uint2*>(g_xh + i + 4) = o2;
}

// -------- kw: fold scales into sign weights (fp16) --------
__global__ void kw_kernel(const float* __restrict__ V,  const float* __restrict__ VR,
                          const float* __restrict__ U,  const float* __restrict__ UR,
                          const float* __restrict__ v2, const float* __restrict__ v2R,
                          const float* __restrict__ u1, const float* __restrict__ u1R) {
    int i = blockIdx.x * blockDim.x + threadIdx.x;
    if (i >= 512 * DIN) return;
    {
        int s = i >> 12, k = i & (DIN - 1);
        float w  = (s < 256) ? V[(size_t)s * DIN + k] : VR[(size_t)(s - 256) * DIN + k];
        float sv = (s < 256) ? v2[k] : v2R[k];
        float sg = (w > 0.f) ? 1.f : ((w < 0.f) ? -1.f : 0.f);
        g_Wv2[i] = __float2half(sg * sv);
    }
    {
        int n = i >> 9, kk = i & 511;
        float w  = (kk < 256) ? U[(size_t)n * 256 + kk] : UR[(size_t)n * 256 + (kk - 256)];
        float su = (kk < 256) ? u1[n] : u1R[n];
        float sg = (w > 0.f) ? 1.f : ((w < 0.f) ? -1.f : 0.f);
        g_Wu2[i] = __float2half(sg * su);
    }
}

// ldmatrix lane-address helpers (80B row stride, conflict-free)
__device__ __forceinline__ uint32_t a_lane_off(int wm, int lane) {
    return (uint32_t)((wm * 32 + (lane & 15)) * 80 + (lane >> 4) * 16);
}
__device__ __forceinline__ uint32_t b_lane_off(int wn, int lane) {
    return (uint32_t)((wn * 64 + ((lane >> 4) << 3) + (lane & 7)) * 80 + (((lane >> 3) & 1) << 4));
}

// register-pipelined mainloop body: chunks c = 0..7 (s16 = c>>2, ntp = c&3)
#define BODY(stg)                                                                     \
    do {                                                                              \
        uint32_t afr[2][2][4];                                                        \
        LDSM_X4(afr[0][0][0], afr[0][0][1], afr[0][0][2], afr[0][0][3], (stg) + aoff);          \
        LDSM_X4(afr[0][1][0], afr[0][1][1], afr[0][1][2], afr[0][1][3], (stg) + aoff + 16 * 80);\
        LDSM_X4(afr[1][0][0], afr[1][0][1], afr[1][0][2], afr[1][0][3], (stg) + aoff + 32);     \
        LDSM_X4(afr[1][1][0], afr[1][1][1], afr[1][1][2], afr[1][1][3], (stg) + aoff + 16 * 80 + 32);\
        uint32_t bfr[2][4];                                                           \
        LDSM_X4(bfr[0][0], bfr[0][1], bfr[0][2], bfr[0][3], (stg) + boff);            \
        _Pragma("unroll")                                                             \
        for (int c = 0; c < 8; c++) {                                                 \
            const int cur = c & 1;                                                    \
            if (c < 7) {                                                              \
                const int nc = c + 1;                                                 \
                LDSM_X4(bfr[cur ^ 1][0], bfr[cur ^ 1][1], bfr[cur ^ 1][2], bfr[cur ^ 1][3],   \
                        (stg) + boff + (nc & 3) * (16 * 80) + (nc >> 2) * 32);        \
            }                                                                         \
            const int s16 = c >> 2, ntp = c & 3;                                      \
            mma_fp16(acc[0][2 * ntp],     afr[s16][0], bfr[cur][0], bfr[cur][1]);     \
            mma_fp16(acc[1][2 * ntp],     afr[s16][1], bfr[cur][0], bfr[cur][1]);     \
            mma_fp16(acc[0][2 * ntp + 1], afr[s16][0], bfr[cur][2], bfr[cur][3]);     \
            mma_fp16(acc[1][2 * ntp + 1], afr[s16][1], bfr[cur][2], bfr[cur][3]);     \
        }                                                                             \
    } while (0)

// -------- k1: h[m, 512] = fp16( (x @ Wv2^T) * (v1*u2) ) --------
// grid (64, 4): br = by>>1, nb = (by&1)*128. CTA 128x128, 8 warps of 32x64, ktile 32.
__global__ void __launch_bounds__(256, 2) k1_kernel(
    const float* __restrict__ v1a, const float* __restrict__ u2a,
    const float* __restrict__ v1b, const float* __restrict__ u2b)
{
    extern __shared__ char sm[];
    const uint32_t smb = smem_u32(sm);
    const int tid = threadIdx.x, warp = tid >> 5, lane = tid & 31;
    const int r = lane >> 2, q = lane & 3;
    const int wm = warp >> 1, wn = warp & 1;
    const int m0 = blockIdx.x * 128;
    const int by = blockIdx.y;
    const int br = by >> 1, nb = (by & 1) * 128;

    float* sc = reinterpret_cast<float*>(sm + 5 * STG);
    if (tid < 128) {
        const float* v1 = br ? v1b : v1a;
        const float* u2 = br ? u2b : u2a;
        sc[tid] = v1[nb + tid] * u2[nb + tid];
    }
    const int row = tid >> 1, half = tid & 1;
    const uint32_t aoff = a_lane_off(wm, lane);
    const uint32_t boff = b_lane_off(wn, lane) + BOFF;

    auto issue = [&](int j) {
        if (j < 128) {
            const int s5 = j % 5, k0 = j * 32;
            uint32_t xd = smb + s5 * STG + row * 80 + half * 32;
            const __half* xs = g_xh + (size_t)(m0 + row) * DIN + k0 + half * 16;
            cpa16(xd, xs);
            cpa16(xd + 16, xs + 8);
            uint32_t bd = smb + s5 * STG + BOFF + row * 80 + half * 32;
            const __half* bsrc = g_Wv2 + (size_t)(br * 256 + nb + row) * DIN + k0 + half * 16;
            cpa16(bd, bsrc);
            cpa16(bd + 16, bsrc + 8);
        }
        CP_COMMIT();
    };
    issue(0); issue(1); issue(2); issue(3);

    float acc[2][8][4];
#pragma unroll
    for (int a = 0; a < 2; a++)
#pragma unroll
        for (int b = 0; b < 8; b++)
#pragma unroll
            for (int c = 0; c < 4; c++) acc[a][b][c] = 0.f;

    for (int it = 0; it < 128; ++it) {
        CP_WAIT3();
        __syncthreads();
        issue(it + 4);
        const uint32_t stg = smb + (it % 5) * STG;
        BODY(stg);
    }

    // epilogue: scale by (v1*u2), convert fp16, store h
#pragma unroll
    for (int mt = 0; mt < 2; mt++) {
#pragma unroll
        for (int nt = 0; nt < 8; nt++) {
            const int rw = m0 + wm * 32 + mt * 16 + r;
            const int cl = wn * 64 + nt * 8 + 2 * q;
            const int col = br * 256 + nb + cl;
            const float s0 = sc[cl], s1 = sc[cl + 1];
            __half2 p0 = __floats2half2_rn(acc[mt][nt][0] * s0, acc[mt][nt][1] * s1);
            __half2 p1 = __floats2half2_rn(acc[mt][nt][2] * s0, acc[mt][nt][3] * s1);
            *reinterpret_cast<uint32_t*>(g_h + (size_t)rw * 512 + col) =
                *reinterpret_cast<uint32_t*>(&p0);
            *reinterpret_cast<uint32_t*>(g_h + (size_t)(rw + 8) * 512 + col) =
                *reinterpret_cast<uint32_t*>(&p1);
        }
    }
}

// -------- k2: y[m, n] = h @ Wu2^T + bias --------
// grid (64, 32). CTA 128x128, 8 warps of 32x64, K=512, ktile 32, 16 iters.
__global__ void __launch_bounds__(256, 2) k2_kernel(
    const float* __restrict__ bias, float* __restrict__ out)
{
    extern __shared__ char sm[];
    const uint32_t smb = smem_u32(sm);
    const int tid = threadIdx.x, warp = tid >> 5, lane = tid & 31;
    const int r = lane >> 2, q = lane & 3;
    const int wm = warp >> 1, wn = warp & 1;
    const int m0 = blockIdx.x * 128;
    const int n0 = blockIdx.y * 128;

    float* bs = reinterpret_cast<float*>(sm + 5 * STG);
    if (tid < 128) bs[tid] = bias[n0 + tid];
    const int row = tid >> 1, half = tid & 1;
    const uint32_t aoff = a_lane_off(wm, lane);
    const uint32_t boff = b_lane_off(wn, lane) + BOFF;

    auto issue = [&](int j) {
        if (j < 16) {
            const int s5 = j % 5, k0 = j * 32;
            uint32_t xd = smb + s5 * STG + row * 80 + half * 32;
            const __half* xs = g_h + (size_t)(m0 + row) * 512 + k0 + half * 16;
            cpa16(xd, xs);
            cpa16(xd + 16, xs + 8);
            uint32_t bd = smb + s5 * STG + BOFF + row * 80 + half * 32;
            const __half* bsrc = g_Wu2 + (size_t)(n0 + row) * 512 + k0 + half * 16;
            cpa16(bd, bsrc);
            cpa16(bd + 16, bsrc + 8);
        }
        CP_COMMIT();
    };
    issue(0); issue(1); issue(2); issue(3);

    float acc[2][8][4];
#pragma unroll
    for (int a = 0; a < 2; a++)
#pragma unroll
        for (int b = 0; b < 8; b++)
#pragma unroll
            for (int c = 0; c < 4; c++) acc[a][b][c] = 0.f;

    for (int it = 0; it < 16; ++it) {
        CP_WAIT3();
        __syncthreads();
        issue(it + 4);
        const uint32_t stg = smb + (it % 5) * STG;
        BODY(stg);
    }

    // epilogue: + bias (u1 folded into Wu2)
#pragma unroll
    for (int mt = 0; mt < 2; mt++) {
#pragma unroll
        for (int nt = 0; nt < 8; nt++) {
            const int rw = m0 + wm * 32 + mt * 16 + r;
            const int cl = wn * 64 + nt * 8 + 2 * q;
            const int col = n0 + cl;
            float2 p0, p1;
            p0.x = acc[mt][nt][0] + bs[cl];
            p0.y = acc[mt][nt][1] + bs[cl + 1];
            p1.x = acc[mt][nt][2] + bs[cl];
            p1.y = acc[mt][nt][3] + bs[cl + 1];
            *reinterpret_cast<float2*>(out + (size_t)rw * DOUT + col) = p0;
            *reinterpret_cast<float2*>(out + (size_t)(rw + 8) * DOUT + col) = p1;
        }
    }
}

extern "C" void kernel_launch(void* const* d_in, const int* in_sizes, int n_in,
                              void* d_out, int out_size) {
    const float* x    = (const float*)d_in[0];
    const float* V    = (const float*)d_in[1];
    const float* U    = (const float*)d_in[2];
    const float* v1   = (const float*)d_in[3];
    const float* v2   = (const float*)d_in[4];
    const float* u1   = (const float*)d_in[5];
    const float* u2   = (const float*)d_in[6];
    const float* VR   = (const float*)d_in[7];
    const float* UR   = (const float*)d_in[8];
    const float* v1R  = (const float*)d_in[9];
    const float* v2R  = (const float*)d_in[10];
    const float* u1R  = (const float*)d_in[11];
    const float* u2R  = (const float*)d_in[12];
    const float* bias = (const float*)d_in[13];
    float* out = (float*)d_out;

    static bool attr_set = false;
    if (!attr_set) {
        cudaFuncSetAttribute(k1_kernel, cudaFuncAttributeMaxDynamicSharedMemorySize, GSMEM);
        cudaFuncSetAttribute(k2_kernel, cudaFuncAttributeMaxDynamicSharedMemorySize, GSMEM);
        attr_set = true;
    }

    kc_kernel<<<(NTOK * (size_t)DIN) / (256 * 8), 256>>>(x);
    kw_kernel<<<8192, 256>>>(V, VR, U, UR, v2, v2R, u1, u1R);
    k1_kernel<<<dim3(NTOK / 128, 4), 256, GSMEM>>>(v1, u2, v1R, u2R);
    k2_kernel<<<dim3(NTOK / 128, DOUT / 128), 256, GSMEM>>>(bias, out);
}